// round 11
// baseline (speedup 1.0000x reference)
#include <cuda_runtime.h>
#include <cuda_fp16.h>
#include <cstdint>

#define NU 50000
#define NI 50000
#define NN 100000            // NU + NI
#define DD 64
#define EE 1600000
#define E2 3200000           // 2*EE directed edges
#define FULLM 0xffffffffu
#define SCAN_BLKS ((NN + 1023) / 1024)   // 98

// ---------------- device scratch (static, no runtime allocation) -----------
__device__ int     g_deg[NN];
__device__ float   g_dinv[NN];
__device__ int     g_rowptr[NN + 1];
__device__ int     g_curpos[NN];
__device__ int     g_bsum[SCAN_BLKS];
__device__ int     g_col[E2];
// 5 fp16 buffers: b0 = dinv*e0, b_k = dinv * x_k  (row = 32 half2 = 128B)
__device__ __half2 g_b0[(size_t)NN * 32];
__device__ __half2 g_b1[(size_t)NN * 32];
__device__ __half2 g_b2[(size_t)NN * 32];
__device__ __half2 g_b3[(size_t)NN * 32];
__device__ __half2 g_b4[(size_t)NN * 32];

// ---------------- graph build ----------------------------------------------

// 4 edges per thread via int4 loads (EE % 4 == 0)
__global__ void k_count(const int* __restrict__ edge) {
    int t = blockIdx.x * blockDim.x + threadIdx.x;
    if (t >= EE / 4) return;
    int4 u4 = ((const int4*)edge)[t];
    int4 i4 = ((const int4*)(edge + EE))[t];
    atomicAdd(&g_deg[u4.x], 1); atomicAdd(&g_deg[u4.y], 1);
    atomicAdd(&g_deg[u4.z], 1); atomicAdd(&g_deg[u4.w], 1);
    atomicAdd(&g_deg[NU + i4.x], 1); atomicAdd(&g_deg[NU + i4.y], 1);
    atomicAdd(&g_deg[NU + i4.z], 1); atomicAdd(&g_deg[NU + i4.w], 1);
}

// phase 1: block-local scan of degrees; also computes dinv (deg already final)
__global__ void k_scan1() {
    __shared__ int wsum[32];
    int idx  = blockIdx.x * 1024 + threadIdx.x;
    int lane = threadIdx.x & 31;
    int wid  = threadIdx.x >> 5;
    int v = (idx < NN) ? g_deg[idx] : 0;
    if (idx < NN) g_dinv[idx] = (v > 0) ? rsqrtf((float)v) : 0.0f;
    int s = v;
    #pragma unroll
    for (int o = 1; o < 32; o <<= 1) {
        int t = __shfl_up_sync(FULLM, s, o);
        if (lane >= o) s += t;
    }
    if (lane == 31) wsum[wid] = s;
    __syncthreads();
    if (wid == 0) {
        int ws = wsum[lane];
        #pragma unroll
        for (int o = 1; o < 32; o <<= 1) {
            int t = __shfl_up_sync(FULLM, ws, o);
            if (lane >= o) ws += t;
        }
        wsum[lane] = ws;
    }
    __syncthreads();
    int off = (wid > 0 ? wsum[wid - 1] : 0);
    if (idx < NN) g_rowptr[idx] = off + s - v;        // block-local exclusive
    if (threadIdx.x == 0) g_bsum[blockIdx.x] = wsum[31];
}

// phase 2+3 fused: warp 0 of each block scans the 98 block sums into smem,
// then all threads add their block offset.
__global__ void k_scan3() {
    __shared__ int sb[SCAN_BLKS];
    int lane = threadIdx.x & 31;
    if (threadIdx.x < 32) {
        int carry = 0;
        #pragma unroll
        for (int base = 0; base < SCAN_BLKS; base += 32) {
            int i2 = base + lane;
            int v = (i2 < SCAN_BLKS) ? g_bsum[i2] : 0;
            int s = v;
            #pragma unroll
            for (int o = 1; o < 32; o <<= 1) {
                int t = __shfl_up_sync(FULLM, s, o);
                if (lane >= o) s += t;
            }
            if (i2 < SCAN_BLKS) sb[i2] = carry + s - v;   // exclusive
            carry += __shfl_sync(FULLM, s, 31);
        }
    }
    __syncthreads();
    int idx = blockIdx.x * blockDim.x + threadIdx.x;
    if (idx >= NN) return;
    int r = g_rowptr[idx] + sb[idx >> 10];
    g_rowptr[idx] = r;
    g_curpos[idx] = r;
    if (idx == 0) g_rowptr[NN] = E2;
}

// CSR fill, 4 edges per thread
__global__ void k_fill(const int* __restrict__ edge) {
    int t = blockIdx.x * blockDim.x + threadIdx.x;
    if (t >= EE / 4) return;
    int4 u4 = ((const int4*)edge)[t];
    int4 i4 = ((const int4*)(edge + EE))[t];
    int us[4] = {u4.x, u4.y, u4.z, u4.w};
    int is[4] = {NU + i4.x, NU + i4.y, NU + i4.z, NU + i4.w};
    #pragma unroll
    for (int k = 0; k < 4; ++k) {
        g_col[atomicAdd(&g_curpos[us[k]], 1)] = is[k];
        g_col[atomicAdd(&g_curpos[is[k]], 1)] = us[k];
    }
}

// ---------------- features -------------------------------------------------

// lane-per-half2: b0 = fp16(dinv * e0)
__global__ void k_initx(const float* __restrict__ ue, const float* __restrict__ ie) {
    int i = blockIdx.x * blockDim.x + threadIdx.x;    // i in [0, NN*32)
    if (i >= NN * 32) return;
    int node = i >> 5;
    int lane = i & 31;
    const float* src = (node < NU) ? (ue + ((size_t)node << 6))
                                   : (ie + ((size_t)(node - NU) << 6));
    float2 v = *((const float2*)src + lane);
    float d = g_dinv[node];
    g_b0[((size_t)node << 5) + lane] = __floats2half2_rn(d * v.x, d * v.y);
}

// warp per node, 2 edges per LDG. Buffer pair selected IN KERNEL by layer id.
// S = sum_j s_prev[col_j]; dst = fp16(dinv^2 * S) = s_layer.
__global__ void k_prop(int layer) {
    const uint2* __restrict__ src;
    uint2*       __restrict__ dst;
    switch (layer) {
        case 0:  src = (const uint2*)g_b0; dst = (uint2*)g_b1; break;
        case 1:  src = (const uint2*)g_b1; dst = (uint2*)g_b2; break;
        case 2:  src = (const uint2*)g_b2; dst = (uint2*)g_b3; break;
        default: src = (const uint2*)g_b3; dst = (uint2*)g_b4; break;
    }
    int node = (blockIdx.x * blockDim.x + threadIdx.x) >> 5;
    if (node >= NN) return;
    int lane = threadIdx.x & 31;
    int half = lane >> 4;      // which edge of the pair this lane handles
    int fpos = lane & 15;      // uint2 position within the 128B row
    int beg = g_rowptr[node];
    int end = g_rowptr[node + 1];
    float s0 = 0.f, s1 = 0.f, s2 = 0.f, s3 = 0.f;
    int j = beg;
    for (; j + 8 <= end; j += 8) {
        int c8 = g_col[j + (lane & 7)];          // lanes 0-7 carry cols j..j+7
        int ca = __shfl_sync(FULLM, c8, half);
        int cb = __shfl_sync(FULLM, c8, 2 + half);
        int cc = __shfl_sync(FULLM, c8, 4 + half);
        int cd = __shfl_sync(FULLM, c8, 6 + half);
        uint2 va = src[((size_t)ca << 4) + fpos];
        uint2 vb = src[((size_t)cb << 4) + fpos];
        uint2 vc = src[((size_t)cc << 4) + fpos];
        uint2 vd = src[((size_t)cd << 4) + fpos];
        __half2 ta = __hadd2(__hadd2(*(__half2*)&va.x, *(__half2*)&vb.x),
                             __hadd2(*(__half2*)&vc.x, *(__half2*)&vd.x));
        __half2 tb = __hadd2(__hadd2(*(__half2*)&va.y, *(__half2*)&vb.y),
                             __hadd2(*(__half2*)&vc.y, *(__half2*)&vd.y));
        float2 fa = __half22float2(ta);
        float2 fb = __half22float2(tb);
        s0 += fa.x; s1 += fa.y; s2 += fb.x; s3 += fb.y;
    }
    for (; j + 2 <= end; j += 2) {               // 2-edge tail steps
        int c = g_col[j + half];
        uint2 v = src[((size_t)c << 4) + fpos];
        float2 fa = __half22float2(*(__half2*)&v.x);
        float2 fb = __half22float2(*(__half2*)&v.y);
        s0 += fa.x; s1 += fa.y; s2 += fb.x; s3 += fb.y;
    }
    if (j < end && half == 0) {                  // odd last edge: half 0 only
        int c = g_col[j];
        uint2 v = src[((size_t)c << 4) + fpos];
        float2 fa = __half22float2(*(__half2*)&v.x);
        float2 fb = __half22float2(*(__half2*)&v.y);
        s0 += fa.x; s1 += fa.y; s2 += fb.x; s3 += fb.y;
    }
    // merge the two half-warps' partial sums (both halves end with full sums)
    s0 += __shfl_xor_sync(FULLM, s0, 16);
    s1 += __shfl_xor_sync(FULLM, s1, 16);
    s2 += __shfl_xor_sync(FULLM, s2, 16);
    s3 += __shfl_xor_sync(FULLM, s3, 16);
    if (half == 1) {                              // 16 lanes cover the 128B row
        float d = g_dinv[node];
        float dd = d * d;
        __half2 w0 = __floats2half2_rn(dd * s0, dd * s1);
        __half2 w1 = __floats2half2_rn(dd * s2, dd * s3);
        uint2 w;
        w.x = *(unsigned*)&w0;
        w.y = *(unsigned*)&w1;
        dst[((size_t)node << 4) + fpos] = w;
    }
}

// warp per (user,item) pair. Reconstruct mean emb on the fly:
// m[r] = e0[r] + sqrt(deg_r) * (b1[r]+b2[r]+b3[r]+b4[r]);  out = dot/25.
__global__ void k_dot(const int* __restrict__ users, const int* __restrict__ items,
                      const float* __restrict__ ue, const float* __restrict__ ie,
                      float* __restrict__ out) {
    int w = (blockIdx.x * blockDim.x + threadIdx.x) >> 5;
    if (w >= 4096) return;
    int lane = threadIdx.x & 31;
    int u  = users[w];
    int iv = items[w];
    int it = NU + iv;

    // user node
    float2 e = *((const float2*)(ue + ((size_t)u << 6)) + lane);
    size_t off = ((size_t)u << 5) + lane;
    float2 f1 = __half22float2(g_b1[off]);
    float2 f2 = __half22float2(g_b2[off]);
    float2 f3 = __half22float2(g_b3[off]);
    float2 f4 = __half22float2(g_b4[off]);
    float r = sqrtf((float)g_deg[u]);
    float ax = e.x + r * (f1.x + f2.x + f3.x + f4.x);
    float ay = e.y + r * (f1.y + f2.y + f3.y + f4.y);

    // item node
    e = *((const float2*)(ie + ((size_t)iv << 6)) + lane);
    off = ((size_t)it << 5) + lane;
    f1 = __half22float2(g_b1[off]);
    f2 = __half22float2(g_b2[off]);
    f3 = __half22float2(g_b3[off]);
    f4 = __half22float2(g_b4[off]);
    r = sqrtf((float)g_deg[it]);
    float bx = e.x + r * (f1.x + f2.x + f3.x + f4.x);
    float by = e.y + r * (f1.y + f2.y + f3.y + f4.y);

    float s = ax * bx + ay * by;
    #pragma unroll
    for (int o = 16; o; o >>= 1) s += __shfl_down_sync(FULLM, s, o);
    if (lane == 0) out[w] = s * 0.04f;   // (1/5)*(1/5) from the two means
}

// ---------------- host launcher --------------------------------------------

extern "C" void kernel_launch(void* const* d_in, const int* in_sizes, int n_in,
                              void* d_out, int out_size) {
    const float* uemb  = (const float*)d_in[0];
    const float* iemb  = (const float*)d_in[1];
    const int*   edge  = (const int*)d_in[2];
    const int*   users = (const int*)d_in[3];
    const int*   items = (const int*)d_in[4];
    float*       out   = (float*)d_out;

    const int T = 256;
    void* degp = nullptr;
    cudaGetSymbolAddress(&degp, g_deg);
    cudaMemsetAsync(degp, 0, NN * sizeof(int));

    k_count<<<((EE / 4) + T - 1) / T, T>>>(edge);
    k_scan1<<<SCAN_BLKS, 1024>>>();                        // + dinv
    k_scan3<<<(NN + T - 1) / T, T>>>();                    // fused bsum scan
    k_fill <<<((EE / 4) + T - 1) / T, T>>>(edge);
    k_initx<<<((NN * 32) + T - 1) / T, T>>>(uemb, iemb);

    // 4 propagation layers: b0 -> b1 -> b2 -> b3 -> b4
    k_prop<<<(NN * 32 + T - 1) / T, T>>>(0);
    k_prop<<<(NN * 32 + T - 1) / T, T>>>(1);
    k_prop<<<(NN * 32 + T - 1) / T, T>>>(2);
    k_prop<<<(NN * 32 + T - 1) / T, T>>>(3);

    k_dot<<<(4096 * 32 + T - 1) / T, T>>>(users, items, uemb, iemb, out);
}

// round 12
// speedup vs baseline: 1.3281x; 1.3281x over previous
#include <cuda_runtime.h>
#include <cuda_fp16.h>
#include <cstdint>

#define NU 50000
#define NI 50000
#define NN 100000            // NU + NI
#define DD 64
#define EE 1600000
#define E2 3200000           // 2*EE directed edges
#define FULLM 0xffffffffu
#define SCAN_BLKS ((NN + 1023) / 1024)   // 98

// ---------------- device scratch (static, no runtime allocation) -----------
__device__ int     g_deg[NN];
__device__ float   g_dinv[NN];
__device__ int     g_rowptr[NN + 1];
__device__ int     g_curpos[NN];
__device__ int     g_bsum[SCAN_BLKS];
__device__ int     g_col[E2];
// ping-pong fp16 gather buffers holding xs = dinv * x  (row = 128B)
__device__ __half2 g_x[(size_t)NN * 32];
__device__ __half2 g_y[(size_t)NN * 32];
__device__ float   g_acc[(size_t)NN * DD];  // running fp32 sum e0 + y1 + ... + y4

// ---------------- graph build ----------------------------------------------

__global__ void k_count(const int* __restrict__ edge) {
    int e = blockIdx.x * blockDim.x + threadIdx.x;
    if (e >= EE) return;
    atomicAdd(&g_deg[edge[e]], 1);
    atomicAdd(&g_deg[NU + edge[EE + e]], 1);
}

// phase 1: block-local scan of degrees; also computes dinv (deg already final)
__global__ void k_scan1() {
    __shared__ int wsum[32];
    int idx  = blockIdx.x * 1024 + threadIdx.x;
    int lane = threadIdx.x & 31;
    int wid  = threadIdx.x >> 5;
    int v = (idx < NN) ? g_deg[idx] : 0;
    if (idx < NN) g_dinv[idx] = (v > 0) ? rsqrtf((float)v) : 0.0f;
    int s = v;
    #pragma unroll
    for (int o = 1; o < 32; o <<= 1) {
        int t = __shfl_up_sync(FULLM, s, o);
        if (lane >= o) s += t;
    }
    if (lane == 31) wsum[wid] = s;
    __syncthreads();
    if (wid == 0) {
        int ws = wsum[lane];
        #pragma unroll
        for (int o = 1; o < 32; o <<= 1) {
            int t = __shfl_up_sync(FULLM, ws, o);
            if (lane >= o) ws += t;
        }
        wsum[lane] = ws;
    }
    __syncthreads();
    int off = (wid > 0 ? wsum[wid - 1] : 0);
    if (idx < NN) g_rowptr[idx] = off + s - v;        // block-local exclusive
    if (threadIdx.x == 0) g_bsum[blockIdx.x] = wsum[31];
}

// phase 2+3 fused: warp 0 of each block scans the 98 block sums into smem,
// then all threads add their block offset.
__global__ void k_scan3() {
    __shared__ int sb[SCAN_BLKS];
    int lane = threadIdx.x & 31;
    if (threadIdx.x < 32) {
        int carry = 0;
        #pragma unroll
        for (int base = 0; base < SCAN_BLKS; base += 32) {
            int i2 = base + lane;
            int v = (i2 < SCAN_BLKS) ? g_bsum[i2] : 0;
            int s = v;
            #pragma unroll
            for (int o = 1; o < 32; o <<= 1) {
                int t = __shfl_up_sync(FULLM, s, o);
                if (lane >= o) s += t;
            }
            if (i2 < SCAN_BLKS) sb[i2] = carry + s - v;   // exclusive
            carry += __shfl_sync(FULLM, s, 31);
        }
    }
    __syncthreads();
    int idx = blockIdx.x * blockDim.x + threadIdx.x;
    if (idx >= NN) return;
    int r = g_rowptr[idx] + sb[idx >> 10];
    g_rowptr[idx] = r;
    g_curpos[idx] = r;
    if (idx == 0) g_rowptr[NN] = E2;
}

// CSR fill, 1 edge per thread (max atomic latency hiding)
__global__ void k_fill(const int* __restrict__ edge) {
    int e = blockIdx.x * blockDim.x + threadIdx.x;
    if (e >= EE) return;
    int u  = edge[e];
    int it = NU + edge[EE + e];
    g_col[atomicAdd(&g_curpos[u],  1)] = it;
    g_col[atomicAdd(&g_curpos[it], 1)] = u;
}

// ---------------- features -------------------------------------------------

// lane-per-half2: acc = e0 (fp32); x = fp16(dinv * e0)
__global__ void k_initx(const float* __restrict__ ue, const float* __restrict__ ie) {
    int i = blockIdx.x * blockDim.x + threadIdx.x;    // i in [0, NN*32)
    if (i >= NN * 32) return;
    int node = i >> 5;
    int lane = i & 31;
    const float* src = (node < NU) ? (ue + ((size_t)node << 6))
                                   : (ie + ((size_t)(node - NU) << 6));
    float2 v = *((const float2*)src + lane);
    *((float2*)(g_acc + ((size_t)node << 6)) + lane) = v;
    float d = g_dinv[node];
    g_x[((size_t)node << 5) + lane] = __floats2half2_rn(d * v.x, d * v.y);
}

// warp per node, 4 edges per LDG: row = 8 x uint4; the warp's four 8-lane
// quarters each gather a different neighbor per load. Cols fetched 16-wide
// per 16 edges. fp16 4-edge trees -> fp32 accum (same precision as before).
// Quarter merge via shfl_xor(8), shfl_xor(16). Epilogue: lanes 0-15 acc RMW,
// lanes 16-23 pack+store the fp16 dst row.
__global__ void k_prop(int flip) {
    const uint4* __restrict__ src = (const uint4*)(flip ? g_y : g_x);
    uint4*       __restrict__ dst = (uint4*)(flip ? g_x : g_y);
    int node = (blockIdx.x * blockDim.x + threadIdx.x) >> 5;
    if (node >= NN) return;
    int lane = threadIdx.x & 31;
    int q    = lane >> 3;      // quarter: which edge of a group of 4
    int fpos = lane & 7;       // uint4 position within the 128B row
    int beg = g_rowptr[node];
    int end = g_rowptr[node + 1];
    float s0=0.f,s1=0.f,s2=0.f,s3=0.f,s4=0.f,s5=0.f,s6=0.f,s7=0.f;
    int j = beg;
    for (; j + 16 <= end; j += 16) {
        int c16 = g_col[j + (lane & 15)];        // lanes 0-15 carry 16 cols
        int ca = __shfl_sync(FULLM, c16, q);
        int cb = __shfl_sync(FULLM, c16, 4 + q);
        int cc = __shfl_sync(FULLM, c16, 8 + q);
        int cd = __shfl_sync(FULLM, c16, 12 + q);
        uint4 va = src[((size_t)ca << 3) + fpos];
        uint4 vb = src[((size_t)cb << 3) + fpos];
        uint4 vc = src[((size_t)cc << 3) + fpos];
        uint4 vd = src[((size_t)cd << 3) + fpos];
        __half2 h0 = __hadd2(__hadd2(*(__half2*)&va.x, *(__half2*)&vb.x),
                             __hadd2(*(__half2*)&vc.x, *(__half2*)&vd.x));
        __half2 h1 = __hadd2(__hadd2(*(__half2*)&va.y, *(__half2*)&vb.y),
                             __hadd2(*(__half2*)&vc.y, *(__half2*)&vd.y));
        __half2 h2 = __hadd2(__hadd2(*(__half2*)&va.z, *(__half2*)&vb.z),
                             __hadd2(*(__half2*)&vc.z, *(__half2*)&vd.z));
        __half2 h3 = __hadd2(__hadd2(*(__half2*)&va.w, *(__half2*)&vb.w),
                             __hadd2(*(__half2*)&vc.w, *(__half2*)&vd.w));
        float2 f0 = __half22float2(h0);
        float2 f1 = __half22float2(h1);
        float2 f2 = __half22float2(h2);
        float2 f3 = __half22float2(h3);
        s0 += f0.x; s1 += f0.y; s2 += f1.x; s3 += f1.y;
        s4 += f2.x; s5 += f2.y; s6 += f3.x; s7 += f3.y;
    }
    // tail: quarter-strided, one edge per quarter per step
    for (int j2 = j + q; j2 < end; j2 += 4) {
        uint4 v = src[((size_t)g_col[j2] << 3) + fpos];
        float2 f0 = __half22float2(*(__half2*)&v.x);
        float2 f1 = __half22float2(*(__half2*)&v.y);
        float2 f2 = __half22float2(*(__half2*)&v.z);
        float2 f3 = __half22float2(*(__half2*)&v.w);
        s0 += f0.x; s1 += f0.y; s2 += f1.x; s3 += f1.y;
        s4 += f2.x; s5 += f2.y; s6 += f3.x; s7 += f3.y;
    }
    // merge the 4 quarters (lanes with equal fpos)
    #pragma unroll
    for (int o = 8; o <= 16; o <<= 1) {
        s0 += __shfl_xor_sync(FULLM, s0, o);
        s1 += __shfl_xor_sync(FULLM, s1, o);
        s2 += __shfl_xor_sync(FULLM, s2, o);
        s3 += __shfl_xor_sync(FULLM, s3, o);
        s4 += __shfl_xor_sync(FULLM, s4, o);
        s5 += __shfl_xor_sync(FULLM, s5, o);
        s6 += __shfl_xor_sync(FULLM, s6, o);
        s7 += __shfl_xor_sync(FULLM, s7, o);
    }
    float d = g_dinv[node];
    if (lane < 16) {
        // acc row = 16 float4; quarter 0 writes even slots (s0..s3),
        // quarter 1 writes odd slots (s4..s7)
        float4* ap = (float4*)g_acc + ((size_t)node << 4) + (fpos << 1) + q;
        float4 a = *ap;
        if (q == 0) { a.x += d*s0; a.y += d*s1; a.z += d*s2; a.w += d*s3; }
        else        { a.x += d*s4; a.y += d*s5; a.z += d*s6; a.w += d*s7; }
        *ap = a;
    } else if (q == 2) {
        float dd = d * d;
        __half2 w0 = __floats2half2_rn(dd*s0, dd*s1);
        __half2 w1 = __floats2half2_rn(dd*s2, dd*s3);
        __half2 w2 = __floats2half2_rn(dd*s4, dd*s5);
        __half2 w3 = __floats2half2_rn(dd*s6, dd*s7);
        uint4 wv;
        wv.x = *(unsigned*)&w0; wv.y = *(unsigned*)&w1;
        wv.z = *(unsigned*)&w2; wv.w = *(unsigned*)&w3;
        dst[((size_t)node << 3) + fpos] = wv;
    }
}

// warp per (user,item) pair: out = dot(acc_u, acc_i) / 25
__global__ void k_dot(const int* __restrict__ users, const int* __restrict__ items,
                      float* __restrict__ out) {
    int w = (blockIdx.x * blockDim.x + threadIdx.x) >> 5;
    if (w >= 4096) return;
    int lane = threadIdx.x & 31;
    int u  = users[w];
    int it = NU + items[w];
    float2 a = *((const float2*)(g_acc + ((size_t)u  << 6)) + lane);
    float2 b = *((const float2*)(g_acc + ((size_t)it << 6)) + lane);
    float s = a.x * b.x + a.y * b.y;
    #pragma unroll
    for (int o = 16; o; o >>= 1) s += __shfl_down_sync(FULLM, s, o);
    if (lane == 0) out[w] = s * 0.04f;   // (1/5)*(1/5) from the two means
}

// ---------------- host launcher --------------------------------------------

extern "C" void kernel_launch(void* const* d_in, const int* in_sizes, int n_in,
                              void* d_out, int out_size) {
    const float* uemb  = (const float*)d_in[0];
    const float* iemb  = (const float*)d_in[1];
    const int*   edge  = (const int*)d_in[2];
    const int*   users = (const int*)d_in[3];
    const int*   items = (const int*)d_in[4];
    float*       out   = (float*)d_out;

    const int T = 256;
    void* degp = nullptr;
    cudaGetSymbolAddress(&degp, g_deg);
    cudaMemsetAsync(degp, 0, NN * sizeof(int));

    k_count<<<(EE + T - 1) / T, T>>>(edge);
    k_scan1<<<SCAN_BLKS, 1024>>>();                        // + dinv
    k_scan3<<<(NN + T - 1) / T, T>>>();                    // fused bsum scan
    k_fill <<<(EE + T - 1) / T, T>>>(edge);
    k_initx<<<((NN * 32) + T - 1) / T, T>>>(uemb, iemb);

    // 4 propagation layers, ping-pong g_x <-> g_y (selected in-kernel)
    k_prop<<<(NN * 32 + T - 1) / T, T>>>(0);
    k_prop<<<(NN * 32 + T - 1) / T, T>>>(1);
    k_prop<<<(NN * 32 + T - 1) / T, T>>>(0);
    k_prop<<<(NN * 32 + T - 1) / T, T>>>(1);

    k_dot<<<(4096 * 32 + T - 1) / T, T>>>(users, items, out);
}

// round 13
// speedup vs baseline: 1.3733x; 1.0340x over previous
#include <cuda_runtime.h>
#include <cuda_fp16.h>
#include <cstdint>

#define NU 50000
#define NI 50000
#define NN 100000            // NU + NI
#define DD 64
#define EE 1600000
#define E2 3200000           // 2*EE directed edges
#define FULLM 0xffffffffu
#define SCAN_BLKS ((NN + 1023) / 1024)   // 98

// ---------------- device scratch (static, no runtime allocation) -----------
__device__ int            g_deg[NN];
__device__ float          g_dinv[NN];
__device__ int            g_rowptr[NN + 1];
__device__ int            g_bsum[SCAN_BLKS];
__device__ unsigned short g_ku[EE];   // occurrence index of edge within user row
__device__ unsigned short g_ki[EE];   // occurrence index of edge within item row
__device__ int            g_col[E2];
// ping-pong fp16 gather buffers holding xs = dinv * x  (row = 128B)
__device__ __half2 g_x[(size_t)NN * 32];
__device__ __half2 g_y[(size_t)NN * 32];
__device__ float   g_acc[(size_t)NN * DD];  // running fp32 sum e0 + y1 + ... + y4

// ---------------- graph build ----------------------------------------------

// count degrees AND record each edge's within-node occurrence index
// (the atomic return value — free). deg stays well below 65536 here.
__global__ void k_count(const int* __restrict__ edge) {
    int e = blockIdx.x * blockDim.x + threadIdx.x;
    if (e >= EE) return;
    int u  = edge[e];
    int it = NU + edge[EE + e];
    g_ku[e] = (unsigned short)atomicAdd(&g_deg[u],  1);
    g_ki[e] = (unsigned short)atomicAdd(&g_deg[it], 1);
}

// phase 1: block-local scan of degrees; also computes dinv (deg already final)
__global__ void k_scan1() {
    __shared__ int wsum[32];
    int idx  = blockIdx.x * 1024 + threadIdx.x;
    int lane = threadIdx.x & 31;
    int wid  = threadIdx.x >> 5;
    int v = (idx < NN) ? g_deg[idx] : 0;
    if (idx < NN) g_dinv[idx] = (v > 0) ? rsqrtf((float)v) : 0.0f;
    int s = v;
    #pragma unroll
    for (int o = 1; o < 32; o <<= 1) {
        int t = __shfl_up_sync(FULLM, s, o);
        if (lane >= o) s += t;
    }
    if (lane == 31) wsum[wid] = s;
    __syncthreads();
    if (wid == 0) {
        int ws = wsum[lane];
        #pragma unroll
        for (int o = 1; o < 32; o <<= 1) {
            int t = __shfl_up_sync(FULLM, ws, o);
            if (lane >= o) ws += t;
        }
        wsum[lane] = ws;
    }
    __syncthreads();
    int off = (wid > 0 ? wsum[wid - 1] : 0);
    if (idx < NN) g_rowptr[idx] = off + s - v;        // block-local exclusive
    if (threadIdx.x == 0) g_bsum[blockIdx.x] = wsum[31];
}

// phase 2+3 fused: warp 0 of each block scans the 98 block sums into smem,
// then all threads add their block offset.
__global__ void k_scan3() {
    __shared__ int sb[SCAN_BLKS];
    int lane = threadIdx.x & 31;
    if (threadIdx.x < 32) {
        int carry = 0;
        #pragma unroll
        for (int base = 0; base < SCAN_BLKS; base += 32) {
            int i2 = base + lane;
            int v = (i2 < SCAN_BLKS) ? g_bsum[i2] : 0;
            int s = v;
            #pragma unroll
            for (int o = 1; o < 32; o <<= 1) {
                int t = __shfl_up_sync(FULLM, s, o);
                if (lane >= o) s += t;
            }
            if (i2 < SCAN_BLKS) sb[i2] = carry + s - v;   // exclusive
            carry += __shfl_sync(FULLM, s, 31);
        }
    }
    __syncthreads();
    int idx = blockIdx.x * blockDim.x + threadIdx.x;
    if (idx >= NN) return;
    g_rowptr[idx] = g_rowptr[idx] + sb[idx >> 10];
    if (idx == 0) g_rowptr[NN] = E2;
}

// CSR fill, ATOMIC-FREE: slot = rowptr[node] + recorded occurrence index
__global__ void k_fill(const int* __restrict__ edge) {
    int e = blockIdx.x * blockDim.x + threadIdx.x;
    if (e >= EE) return;
    int u  = edge[e];
    int it = NU + edge[EE + e];
    g_col[g_rowptr[u]  + (int)g_ku[e]] = it;
    g_col[g_rowptr[it] + (int)g_ki[e]] = u;
}

// ---------------- features -------------------------------------------------

// lane-per-half2: acc = e0 (fp32); x = fp16(dinv * e0)
__global__ void k_initx(const float* __restrict__ ue, const float* __restrict__ ie) {
    int i = blockIdx.x * blockDim.x + threadIdx.x;    // i in [0, NN*32)
    if (i >= NN * 32) return;
    int node = i >> 5;
    int lane = i & 31;
    const float* src = (node < NU) ? (ue + ((size_t)node << 6))
                                   : (ie + ((size_t)(node - NU) << 6));
    float2 v = *((const float2*)src + lane);
    *((float2*)(g_acc + ((size_t)node << 6)) + lane) = v;
    float d = g_dinv[node];
    g_x[((size_t)node << 5) + lane] = __floats2half2_rn(d * v.x, d * v.y);
}

// warp per node, 2 edges per LDG (R10 proven version): each half-warp
// (16 lanes x uint2 = 128B row) gathers a different neighbor per load.
// Col indices fetched 8-wide and distributed via shfl.idx. fp16 4-edge
// trees -> fp32 accum. Halves merged via shfl_xor(16). Epilogue split:
// half 0 -> acc RMW, half 1 -> dst store.
__global__ void k_prop(int flip) {
    const uint2* __restrict__ src = (const uint2*)(flip ? g_y : g_x);
    uint2*       __restrict__ dst = (uint2*)(flip ? g_x : g_y);
    int node = (blockIdx.x * blockDim.x + threadIdx.x) >> 5;
    if (node >= NN) return;
    int lane = threadIdx.x & 31;
    int half = lane >> 4;      // which edge of the pair this lane handles
    int fpos = lane & 15;      // uint2 position within the 128B row
    int beg = g_rowptr[node];
    int end = g_rowptr[node + 1];
    float s0 = 0.f, s1 = 0.f, s2 = 0.f, s3 = 0.f;
    int j = beg;
    for (; j + 8 <= end; j += 8) {
        int c8 = g_col[j + (lane & 7)];          // lanes 0-7 carry cols j..j+7
        int ca = __shfl_sync(FULLM, c8, half);
        int cb = __shfl_sync(FULLM, c8, 2 + half);
        int cc = __shfl_sync(FULLM, c8, 4 + half);
        int cd = __shfl_sync(FULLM, c8, 6 + half);
        uint2 va = src[((size_t)ca << 4) + fpos];
        uint2 vb = src[((size_t)cb << 4) + fpos];
        uint2 vc = src[((size_t)cc << 4) + fpos];
        uint2 vd = src[((size_t)cd << 4) + fpos];
        __half2 ta = __hadd2(__hadd2(*(__half2*)&va.x, *(__half2*)&vb.x),
                             __hadd2(*(__half2*)&vc.x, *(__half2*)&vd.x));
        __half2 tb = __hadd2(__hadd2(*(__half2*)&va.y, *(__half2*)&vb.y),
                             __hadd2(*(__half2*)&vc.y, *(__half2*)&vd.y));
        float2 fa = __half22float2(ta);
        float2 fb = __half22float2(tb);
        s0 += fa.x; s1 += fa.y; s2 += fb.x; s3 += fb.y;
    }
    for (; j + 2 <= end; j += 2) {               // 2-edge tail steps
        int c = g_col[j + half];
        uint2 v = src[((size_t)c << 4) + fpos];
        float2 fa = __half22float2(*(__half2*)&v.x);
        float2 fb = __half22float2(*(__half2*)&v.y);
        s0 += fa.x; s1 += fa.y; s2 += fb.x; s3 += fb.y;
    }
    if (j < end && half == 0) {                  // odd last edge: half 0 only
        int c = g_col[j];
        uint2 v = src[((size_t)c << 4) + fpos];
        float2 fa = __half22float2(*(__half2*)&v.x);
        float2 fb = __half22float2(*(__half2*)&v.y);
        s0 += fa.x; s1 += fa.y; s2 += fb.x; s3 += fb.y;
    }
    // merge the two half-warps' partial sums (both halves end with full sums)
    s0 += __shfl_xor_sync(FULLM, s0, 16);
    s1 += __shfl_xor_sync(FULLM, s1, 16);
    s2 += __shfl_xor_sync(FULLM, s2, 16);
    s3 += __shfl_xor_sync(FULLM, s3, 16);
    float d = g_dinv[node];
    if (half == 0) {
        float4* ap = (float4*)g_acc + ((size_t)node << 4) + fpos;
        float4 a = *ap;
        a.x += d * s0; a.y += d * s1; a.z += d * s2; a.w += d * s3;
        *ap = a;
    } else {
        float dd = d * d;
        __half2 w0 = __floats2half2_rn(dd * s0, dd * s1);
        __half2 w1 = __floats2half2_rn(dd * s2, dd * s3);
        uint2 w;
        w.x = *(unsigned*)&w0;
        w.y = *(unsigned*)&w1;
        dst[((size_t)node << 4) + fpos] = w;
    }
}

// warp per (user,item) pair: out = dot(acc_u, acc_i) / 25
__global__ void k_dot(const int* __restrict__ users, const int* __restrict__ items,
                      float* __restrict__ out) {
    int w = (blockIdx.x * blockDim.x + threadIdx.x) >> 5;
    if (w >= 4096) return;
    int lane = threadIdx.x & 31;
    int u  = users[w];
    int it = NU + items[w];
    float2 a = *((const float2*)(g_acc + ((size_t)u  << 6)) + lane);
    float2 b = *((const float2*)(g_acc + ((size_t)it << 6)) + lane);
    float s = a.x * b.x + a.y * b.y;
    #pragma unroll
    for (int o = 16; o; o >>= 1) s += __shfl_down_sync(FULLM, s, o);
    if (lane == 0) out[w] = s * 0.04f;   // (1/5)*(1/5) from the two means
}

// ---------------- host launcher --------------------------------------------

extern "C" void kernel_launch(void* const* d_in, const int* in_sizes, int n_in,
                              void* d_out, int out_size) {
    const float* uemb  = (const float*)d_in[0];
    const float* iemb  = (const float*)d_in[1];
    const int*   edge  = (const int*)d_in[2];
    const int*   users = (const int*)d_in[3];
    const int*   items = (const int*)d_in[4];
    float*       out   = (float*)d_out;

    const int T = 256;
    void* degp = nullptr;
    cudaGetSymbolAddress(&degp, g_deg);
    cudaMemsetAsync(degp, 0, NN * sizeof(int));

    k_count<<<(EE + T - 1) / T, T>>>(edge);                // launch 1
    k_scan1<<<SCAN_BLKS, 1024>>>();                        // launch 2 (+dinv)
    k_scan3<<<(NN + T - 1) / T, T>>>();                    // launch 3
    k_fill <<<(EE + T - 1) / T, T>>>(edge);                // launch 4
    k_initx<<<((NN * 32) + T - 1) / T, T>>>(uemb, iemb);   // launch 5 <- profiled

    // 4 propagation layers, ping-pong g_x <-> g_y (selected in-kernel)
    k_prop<<<(NN * 32 + T - 1) / T, T>>>(0);
    k_prop<<<(NN * 32 + T - 1) / T, T>>>(1);
    k_prop<<<(NN * 32 + T - 1) / T, T>>>(0);
    k_prop<<<(NN * 32 + T - 1) / T, T>>>(1);

    k_dot<<<(4096 * 32 + T - 1) / T, T>>>(users, items, out);
}

// round 14
// speedup vs baseline: 1.4727x; 1.0724x over previous
#include <cuda_runtime.h>
#include <cuda_fp16.h>
#include <cstdint>

#define NU 50000
#define NI 50000
#define NN 100000            // NU + NI
#define DD 64
#define EE 1600000
#define E2 3200000           // 2*EE directed edges
#define NB 4096              // batch pairs
#define FULLM 0xffffffffu
#define SCAN_BLKS ((NN + 1023) / 1024)   // 98

// ---------------- device scratch (static, no runtime allocation) -----------
__device__ int            g_deg[NN];
__device__ float          g_dinv[NN];
__device__ int            g_rowptr[NN + 1];
__device__ int            g_bsum[SCAN_BLKS];
__device__ unsigned short g_ku[EE];   // occurrence index of edge within user row
__device__ unsigned short g_ki[EE];   // occurrence index of edge within item row
__device__ int            g_col[E2];
__device__ unsigned char  g_flag[NN]; // 1 if node appears in users/items sample
// ping-pong fp16 gather buffers holding xs = dinv * x  (row = 128B)
__device__ __half2 g_x[(size_t)NN * 32];
__device__ __half2 g_y[(size_t)NN * 32];
__device__ float   g_acc[(size_t)NN * DD];  // fp32 sum, maintained ONLY at flagged nodes

// ---------------- graph build ----------------------------------------------

// count degrees AND record each edge's within-node occurrence index
__global__ void k_count(const int* __restrict__ edge) {
    int e = blockIdx.x * blockDim.x + threadIdx.x;
    if (e >= EE) return;
    int u  = edge[e];
    int it = NU + edge[EE + e];
    g_ku[e] = (unsigned short)atomicAdd(&g_deg[u],  1);
    g_ki[e] = (unsigned short)atomicAdd(&g_deg[it], 1);
}

// mark sampled nodes (races benign: all write 1)
__global__ void k_flag(const int* __restrict__ users, const int* __restrict__ items) {
    int i = blockIdx.x * blockDim.x + threadIdx.x;
    if (i < NB)           g_flag[users[i]] = 1;
    else if (i < 2 * NB)  g_flag[NU + items[i - NB]] = 1;
}

// phase 1: block-local scan of degrees; also computes dinv (deg already final)
__global__ void k_scan1() {
    __shared__ int wsum[32];
    int idx  = blockIdx.x * 1024 + threadIdx.x;
    int lane = threadIdx.x & 31;
    int wid  = threadIdx.x >> 5;
    int v = (idx < NN) ? g_deg[idx] : 0;
    if (idx < NN) g_dinv[idx] = (v > 0) ? rsqrtf((float)v) : 0.0f;
    int s = v;
    #pragma unroll
    for (int o = 1; o < 32; o <<= 1) {
        int t = __shfl_up_sync(FULLM, s, o);
        if (lane >= o) s += t;
    }
    if (lane == 31) wsum[wid] = s;
    __syncthreads();
    if (wid == 0) {
        int ws = wsum[lane];
        #pragma unroll
        for (int o = 1; o < 32; o <<= 1) {
            int t = __shfl_up_sync(FULLM, ws, o);
            if (lane >= o) ws += t;
        }
        wsum[lane] = ws;
    }
    __syncthreads();
    int off = (wid > 0 ? wsum[wid - 1] : 0);
    if (idx < NN) g_rowptr[idx] = off + s - v;        // block-local exclusive
    if (threadIdx.x == 0) g_bsum[blockIdx.x] = wsum[31];
}

// phase 2+3 fused: warp 0 of each block scans the 98 block sums into smem,
// then all threads add their block offset.
__global__ void k_scan3() {
    __shared__ int sb[SCAN_BLKS];
    int lane = threadIdx.x & 31;
    if (threadIdx.x < 32) {
        int carry = 0;
        #pragma unroll
        for (int base = 0; base < SCAN_BLKS; base += 32) {
            int i2 = base + lane;
            int v = (i2 < SCAN_BLKS) ? g_bsum[i2] : 0;
            int s = v;
            #pragma unroll
            for (int o = 1; o < 32; o <<= 1) {
                int t = __shfl_up_sync(FULLM, s, o);
                if (lane >= o) s += t;
            }
            if (i2 < SCAN_BLKS) sb[i2] = carry + s - v;   // exclusive
            carry += __shfl_sync(FULLM, s, 31);
        }
    }
    __syncthreads();
    int idx = blockIdx.x * blockDim.x + threadIdx.x;
    if (idx >= NN) return;
    g_rowptr[idx] = g_rowptr[idx] + sb[idx >> 10];
    if (idx == 0) g_rowptr[NN] = E2;
}

// CSR fill, atomic-free: slot = rowptr[node] + recorded occurrence index
__global__ void k_fill(const int* __restrict__ edge) {
    int e = blockIdx.x * blockDim.x + threadIdx.x;
    if (e >= EE) return;
    int u  = edge[e];
    int it = NU + edge[EE + e];
    g_col[g_rowptr[u]  + (int)g_ku[e]] = it;
    g_col[g_rowptr[it] + (int)g_ki[e]] = u;
}

// ---------------- features -------------------------------------------------

// lane-per-half2: x = fp16(dinv * e0); acc = e0 ONLY at flagged nodes
__global__ void k_initx(const float* __restrict__ ue, const float* __restrict__ ie) {
    int i = blockIdx.x * blockDim.x + threadIdx.x;    // i in [0, NN*32)
    if (i >= NN * 32) return;
    int node = i >> 5;
    int lane = i & 31;
    const float* src = (node < NU) ? (ue + ((size_t)node << 6))
                                   : (ie + ((size_t)(node - NU) << 6));
    float2 v = *((const float2*)src + lane);
    if (g_flag[node])
        *((float2*)(g_acc + ((size_t)node << 6)) + lane) = v;
    float d = g_dinv[node];
    g_x[((size_t)node << 5) + lane] = __floats2half2_rn(d * v.x, d * v.y);
}

// warp per node, 2 edges per LDG: each half-warp (16 lanes x uint2 = 128B row)
// gathers a different neighbor per load. Col indices fetched 8-wide and
// distributed via shfl.idx. fp16 4-edge trees -> fp32 accum. Halves merged
// via shfl_xor(16). Epilogue: half 1 always stores fp16 dst; half 0 updates
// fp32 acc ONLY if this node is in the sample.
__global__ void k_prop(int flip) {
    const uint2* __restrict__ src = (const uint2*)(flip ? g_y : g_x);
    uint2*       __restrict__ dst = (uint2*)(flip ? g_x : g_y);
    int node = (blockIdx.x * blockDim.x + threadIdx.x) >> 5;
    if (node >= NN) return;
    int lane = threadIdx.x & 31;
    int half = lane >> 4;      // which edge of the pair this lane handles
    int fpos = lane & 15;      // uint2 position within the 128B row
    int beg = g_rowptr[node];
    int end = g_rowptr[node + 1];
    float s0 = 0.f, s1 = 0.f, s2 = 0.f, s3 = 0.f;
    int j = beg;
    for (; j + 8 <= end; j += 8) {
        int c8 = g_col[j + (lane & 7)];          // lanes 0-7 carry cols j..j+7
        int ca = __shfl_sync(FULLM, c8, half);
        int cb = __shfl_sync(FULLM, c8, 2 + half);
        int cc = __shfl_sync(FULLM, c8, 4 + half);
        int cd = __shfl_sync(FULLM, c8, 6 + half);
        uint2 va = src[((size_t)ca << 4) + fpos];
        uint2 vb = src[((size_t)cb << 4) + fpos];
        uint2 vc = src[((size_t)cc << 4) + fpos];
        uint2 vd = src[((size_t)cd << 4) + fpos];
        __half2 ta = __hadd2(__hadd2(*(__half2*)&va.x, *(__half2*)&vb.x),
                             __hadd2(*(__half2*)&vc.x, *(__half2*)&vd.x));
        __half2 tb = __hadd2(__hadd2(*(__half2*)&va.y, *(__half2*)&vb.y),
                             __hadd2(*(__half2*)&vc.y, *(__half2*)&vd.y));
        float2 fa = __half22float2(ta);
        float2 fb = __half22float2(tb);
        s0 += fa.x; s1 += fa.y; s2 += fb.x; s3 += fb.y;
    }
    for (; j + 2 <= end; j += 2) {               // 2-edge tail steps
        int c = g_col[j + half];
        uint2 v = src[((size_t)c << 4) + fpos];
        float2 fa = __half22float2(*(__half2*)&v.x);
        float2 fb = __half22float2(*(__half2*)&v.y);
        s0 += fa.x; s1 += fa.y; s2 += fb.x; s3 += fb.y;
    }
    if (j < end && half == 0) {                  // odd last edge: half 0 only
        int c = g_col[j];
        uint2 v = src[((size_t)c << 4) + fpos];
        float2 fa = __half22float2(*(__half2*)&v.x);
        float2 fb = __half22float2(*(__half2*)&v.y);
        s0 += fa.x; s1 += fa.y; s2 += fb.x; s3 += fb.y;
    }
    // merge the two half-warps' partial sums (both halves end with full sums)
    s0 += __shfl_xor_sync(FULLM, s0, 16);
    s1 += __shfl_xor_sync(FULLM, s1, 16);
    s2 += __shfl_xor_sync(FULLM, s2, 16);
    s3 += __shfl_xor_sync(FULLM, s3, 16);
    float d = g_dinv[node];
    if (half == 0) {
        if (g_flag[node]) {                      // warp-uniform branch
            float4* ap = (float4*)g_acc + ((size_t)node << 4) + fpos;
            float4 a = *ap;
            a.x += d * s0; a.y += d * s1; a.z += d * s2; a.w += d * s3;
            *ap = a;
        }
    } else {
        float dd = d * d;
        __half2 w0 = __floats2half2_rn(dd * s0, dd * s1);
        __half2 w1 = __floats2half2_rn(dd * s2, dd * s3);
        uint2 w;
        w.x = *(unsigned*)&w0;
        w.y = *(unsigned*)&w1;
        dst[((size_t)node << 4) + fpos] = w;
    }
}

// warp per (user,item) pair: out = dot(acc_u, acc_i) / 25
__global__ void k_dot(const int* __restrict__ users, const int* __restrict__ items,
                      float* __restrict__ out) {
    int w = (blockIdx.x * blockDim.x + threadIdx.x) >> 5;
    if (w >= NB) return;
    int lane = threadIdx.x & 31;
    int u  = users[w];
    int it = NU + items[w];
    float2 a = *((const float2*)(g_acc + ((size_t)u  << 6)) + lane);
    float2 b = *((const float2*)(g_acc + ((size_t)it << 6)) + lane);
    float s = a.x * b.x + a.y * b.y;
    #pragma unroll
    for (int o = 16; o; o >>= 1) s += __shfl_down_sync(FULLM, s, o);
    if (lane == 0) out[w] = s * 0.04f;   // (1/5)*(1/5) from the two means
}

// ---------------- host launcher --------------------------------------------

extern "C" void kernel_launch(void* const* d_in, const int* in_sizes, int n_in,
                              void* d_out, int out_size) {
    const float* uemb  = (const float*)d_in[0];
    const float* iemb  = (const float*)d_in[1];
    const int*   edge  = (const int*)d_in[2];
    const int*   users = (const int*)d_in[3];
    const int*   items = (const int*)d_in[4];
    float*       out   = (float*)d_out;

    const int T = 256;
    void* p = nullptr;
    cudaGetSymbolAddress(&p, g_deg);
    cudaMemsetAsync(p, 0, NN * sizeof(int));
    cudaGetSymbolAddress(&p, g_flag);
    cudaMemsetAsync(p, 0, NN);

    k_count<<<(EE + T - 1) / T, T>>>(edge);
    k_flag <<<(2 * NB + T - 1) / T, T>>>(users, items);
    k_scan1<<<SCAN_BLKS, 1024>>>();                        // + dinv
    k_scan3<<<(NN + T - 1) / T, T>>>();
    k_fill <<<(EE + T - 1) / T, T>>>(edge);
    k_initx<<<((NN * 32) + T - 1) / T, T>>>(uemb, iemb);

    // 4 propagation layers, ping-pong g_x <-> g_y (selected in-kernel)
    k_prop<<<(NN * 32 + T - 1) / T, T>>>(0);
    k_prop<<<(NN * 32 + T - 1) / T, T>>>(1);
    k_prop<<<(NN * 32 + T - 1) / T, T>>>(0);
    k_prop<<<(NN * 32 + T - 1) / T, T>>>(1);

    k_dot<<<(NB * 32 + T - 1) / T, T>>>(users, items, out);
}